// round 11
// baseline (speedup 1.0000x reference)
#include <cuda_runtime.h>
#include <cstdint>
#include <math.h>

#define NB 32
#define NS 512
#define NI 128
#define NH 128
#define NO 32
#define NG 384   // 3*H
#define NCONS 116            // consumer CTAs (148-32)
#define FLAG_STEP 8
#define NFLAG (NS / FLAG_STEP)     // 64
#define NMTILE 256                 // 32 b x 8 schunks
#define NGJOB 768                  // 256 m-tiles x 3 n-tiles

// Scratch (device globals; no allocation in kernel_launch)
__device__ float g_ih[(size_t)NB * NS * NG];          // [b][s][g]
__device__ float g_coef[(size_t)NS * NB * 4 * NH];    // [s*32+b][plane][j]
__device__ float g_wT[(size_t)NH * NG];               // [i][c] = W_hh[c][i]
__device__ unsigned g_flag[NFLAG];                    // scan progress (0..32)
__device__ unsigned g_ihflag[NMTILE];                 // ih chunk ready (0..3)

// ---------------- helpers ----------------
__device__ __forceinline__ float ex2f(float x) {
    float r; asm("ex2.approx.f32 %0, %1;" : "=f"(r) : "f"(x)); return r;
}
__device__ __forceinline__ float rcpf(float x) {
    float r; asm("rcp.approx.f32 %0, %1;" : "=f"(r) : "f"(x)); return r;
}
__device__ __forceinline__ float sigf(float x) {
    return rcpf(1.0f + ex2f(-1.4426950408889634f * x));
}
__device__ __forceinline__ float tanh_fast(float x) {
    float e = ex2f(2.8853900817779268f * x);   // e^{2x}
    return 1.0f - 2.0f * rcpf(e + 1.0f);
}
__device__ __forceinline__ unsigned long long pack2(float lo, float hi) {
    unsigned long long r;
    asm("mov.b64 %0, {%1,%2};" : "=l"(r)
        : "r"(__float_as_uint(lo)), "r"(__float_as_uint(hi)));
    return r;
}
__device__ __forceinline__ void unpack2(unsigned long long v, float& lo, float& hi) {
    unsigned a, b;
    asm("mov.b64 {%0,%1}, %2;" : "=r"(a), "=r"(b) : "l"(v));
    lo = __uint_as_float(a); hi = __uint_as_float(b);
}
__device__ __forceinline__ void ffma2(unsigned long long& acc,
                                      unsigned long long a, unsigned long long b) {
    asm("fma.rn.f32x2 %0, %1, %2, %0;" : "+l"(acc) : "l"(a), "l"(b));
}
__device__ __forceinline__ unsigned long long addf2(unsigned long long a,
                                                    unsigned long long b) {
    unsigned long long r;
    asm("add.rn.f32x2 %0, %1, %2;" : "=l"(r) : "l"(a), "l"(b));
    return r;
}
__device__ __forceinline__ unsigned ld_acquire(const unsigned* p) {
    unsigned v;
    asm volatile("ld.acquire.gpu.global.b32 %0, [%1];" : "=r"(v) : "l"(p));
    return v;
}
__device__ __forceinline__ void red_add_release(unsigned* p, unsigned v) {
    asm volatile("red.release.gpu.global.add.u32 [%0], %1;" :: "l"(p), "r"(v));
}

// ---------------- init: zero flags + transpose W_hh ----------------
__global__ void __launch_bounds__(256) init_kernel(const float* __restrict__ W_hh) {
    int t = blockIdx.x * 256 + threadIdx.x;
    if (t < NFLAG) g_flag[t] = 0u;
    if (t < NMTILE) g_ihflag[t] = 0u;
    for (int o = t; o < NH * NG; o += gridDim.x * 256) {
        int i = o / NG, c = o - i * NG;
        g_wT[o] = W_hh[(size_t)c * NH + i];
    }
}

// ---------------- one ih-GEMM tile: 64(m) x 128(n), K=128 ----------------
// Threads 0..255 compute; all 384 hit the barriers.
__device__ void gemm_tile(const float* __restrict__ x, const float* __restrict__ W_ih,
                          const float* __restrict__ b_ih,
                          int m0, int n0, int tid, float* As, float* Bs)
{
    const bool act = tid < 256;
    const int tx = tid & 15;
    const int ty = tid >> 4;
    const int lm = tid >> 3;
    const int lk = tid & 7;

    unsigned long long acc[4][4];
#pragma unroll
    for (int a = 0; a < 4; a++)
#pragma unroll
        for (int c = 0; c < 4; c++) acc[a][c] = 0ull;

    const float4* x4 = (const float4*)x;
    const float4* w4 = (const float4*)W_ih;
    float4 ra[2], rb[4];

    if (act) {
#pragma unroll
        for (int r = 0; r < 2; r++)
            ra[r] = x4[(size_t)(m0 + lm + r * 32) * 32 + lk];
#pragma unroll
        for (int r = 0; r < 4; r++)
            rb[r] = w4[(size_t)(n0 + lm + r * 32) * 32 + lk];
    }
#pragma unroll
    for (int kc = 0; kc < 4; kc++) {
        __syncthreads();
        if (act) {
#pragma unroll
            for (int r = 0; r < 2; r++)
                ((float4*)As)[tid + r * 256] = ra[r];
#pragma unroll
            for (int r = 0; r < 4; r++) {
                int n = lm + r * 32;
                Bs[(lk * 4 + 0) * 128 + n] = rb[r].x;
                Bs[(lk * 4 + 1) * 128 + n] = rb[r].y;
                Bs[(lk * 4 + 2) * 128 + n] = rb[r].z;
                Bs[(lk * 4 + 3) * 128 + n] = rb[r].w;
            }
        }
        __syncthreads();
        if (act && kc < 3) {
#pragma unroll
            for (int r = 0; r < 2; r++)
                ra[r] = x4[(size_t)(m0 + lm + r * 32) * 32 + (kc + 1) * 8 + lk];
#pragma unroll
            for (int r = 0; r < 4; r++)
                rb[r] = w4[(size_t)(n0 + lm + r * 32) * 32 + (kc + 1) * 8 + lk];
        }
        if (act) {
#pragma unroll 8
            for (int k = 0; k < 32; k++) {
                unsigned long long a2[4];
#pragma unroll
                for (int mm = 0; mm < 4; mm++) {
                    float av = As[(ty * 4 + mm) * 32 + k];
                    a2[mm] = pack2(av, av);
                }
                const ulonglong2* bp = (const ulonglong2*)(Bs + k * 128 + tx * 8);
                ulonglong2 p0 = bp[0], p1 = bp[1];
                unsigned long long b2[4] = {p0.x, p0.y, p1.x, p1.y};
#pragma unroll
                for (int mm = 0; mm < 4; mm++)
#pragma unroll
                    for (int c = 0; c < 4; c++)
                        ffma2(acc[mm][c], a2[mm], b2[c]);
            }
        }
    }
    if (act) {
#pragma unroll
        for (int mm = 0; mm < 4; mm++) {
            int m = m0 + ty * 4 + mm;
            float* orow = g_ih + (size_t)m * NG + n0 + tx * 8;
            float vals[8];
#pragma unroll
            for (int c = 0; c < 4; c++) {
                float lo, hi;
                unpack2(acc[mm][c], lo, hi);
                int n = n0 + tx * 8 + c * 2;
                vals[c * 2]     = lo + b_ih[n];
                vals[c * 2 + 1] = hi + b_ih[n + 1];
            }
            ((float4*)orow)[0] = make_float4(vals[0], vals[1], vals[2], vals[3]);
            ((float4*)orow)[1] = make_float4(vals[4], vals[5], vals[6], vals[7]);
        }
        __threadfence();
    }
    __syncthreads();
}

// ---------------- Mega kernel: fused gemm + scan + jac ----------------
__global__ void __launch_bounds__(384, 1) mega_kernel(
    const float* __restrict__ x,    const float* __restrict__ W_ih,
    const float* __restrict__ b_ih,
    const float* __restrict__ W_hh, const float* __restrict__ b_hh,
    const float* __restrict__ W_y,  const float* __restrict__ b_y,
    float* __restrict__ out)
{
    const int tid = threadIdx.x;
    __shared__ __align__(16) float smem_pool[32 * 128 + 64 * 32];  // 24 KB union

    if (blockIdx.x < NB) {
        // ================= PRODUCER: GRU scan for batch b (R10 form) =================
        const int b = blockIdx.x;
        const int g = tid;
        const int role = g >> 7;        // 0: r, 1: z, 2: n (warp-uniform)
        const int j = g & 127;

        float* h_sh = smem_pool;                          // [128]
        float2* rp_sh = (float2*)(smem_pool + 128);       // [128]
        float2* zp_sh = (float2*)(smem_pool + 128 + 256); // [128]

        unsigned long long w2[64];
        const unsigned long long* wrow =
            (const unsigned long long*)(W_hh + (size_t)g * NH);
#pragma unroll
        for (int k2 = 0; k2 < 64; k2++) w2[k2] = wrow[k2];
        const float bh = b_hh[g];

        if (g < NH) h_sh[g] = 0.0f;

        const float* ihp = g_ih + (size_t)b * NS * NG;
        // wait for ih chunk 0
        if (tid == 0) {
            while (ld_acquire(&g_ihflag[b * 8]) < 3u) __nanosleep(64);
        }
        __syncthreads();
        float ih_next = ihp[g];

        for (int s = 0; s < NS; s++) {
            float ih_cur = ih_next;
            if (s + 1 < NS) {
                if (((s + 1) & 63) == 0) {
                    if (tid == 0) {
                        int mt = b * 8 + ((s + 1) >> 6);
                        while (ld_acquire(&g_ihflag[mt]) < 3u) __nanosleep(64);
                    }
                    __syncthreads();
                }
                ih_next = ihp[(size_t)(s + 1) * NG + g];
            }

            // hh[g] = W_hh[g,:] . h + b_hh[g]  (f32x2)
            unsigned long long acc[4] = {0ull, 0ull, 0ull, 0ull};
            const ulonglong2* h4 = (const ulonglong2*)h_sh;
#pragma unroll
            for (int k4 = 0; k4 < 32; k4++) {
                ulonglong2 hv = h4[k4];
                ffma2(acc[(2 * k4) & 3],     w2[2 * k4],     hv.x);
                ffma2(acc[(2 * k4 + 1) & 3], w2[2 * k4 + 1], hv.y);
            }
            unsigned long long t01 = addf2(acc[0], acc[1]);
            unsigned long long t23 = addf2(acc[2], acc[3]);
            unsigned long long tt  = addf2(t01, t23);
            float lo, hi;
            unpack2(tt, lo, hi);
            float sum = lo + hi + bh;

            const size_t cb = ((size_t)(s * NB + b)) * (4 * NH);
            if (role == 0) {
                float r = sigf(ih_cur + sum);
                rp_sh[j] = make_float2(r, r * (1.0f - r));
                asm volatile("bar.arrive 1, 384;" ::: "memory");
            } else if (role == 1) {
                float z = sigf(ih_cur + sum);
                zp_sh[j] = make_float2(z, z * (1.0f - z));
                g_coef[cb + 3 * NH + j] = z;
                asm volatile("bar.arrive 1, 384;" ::: "memory");
            } else {
                float M = sum;
                float hp = h_sh[j];                 // own slot, pre-sync safe
                asm volatile("bar.sync 1, 384;" ::: "memory");
                float2 rp = rp_sh[j];
                float2 zp = zp_sh[j];
                float n = tanh_fast(ih_cur + rp.x * M);
                float c67 = (1.0f - n * n) * (1.0f - zp.x);
                g_coef[cb + j]          = rp.y * M * c67;     // cr
                g_coef[cb + NH + j]     = rp.x * c67;         // cn
                g_coef[cb + 2 * NH + j] = zp.y * (hp - n);    // cz
                h_sh[j] = n + zp.x * (hp - n);                // h_new
            }
            __syncthreads();
            // coef stores happen-before this bar; red.release gives consumers'
            // acquire loads transitive visibility (no MEMBAR needed).
            if (tid == 0 && (s & (FLAG_STEP - 1)) == FLAG_STEP - 1)
                red_add_release(&g_flag[s >> 3], 1u);
        }

        // y = h_last @ W_y^T + b_y
        if (g < NO) {
            float a = b_y[g];
            const float* wy = W_y + (size_t)g * NH;
#pragma unroll
            for (int k = 0; k < NH; k++) a = fmaf(wy[k], h_sh[k], a);
            out[b * NO + g] = a;
        }
    } else {
        // ============ CONSUMER: gemm jobs, then dual-b Jacobian ============
        const int c0 = blockIdx.x - NB;     // 0..115
        float* Bs = smem_pool;              // [32*128]
        float* As = smem_pool + 32 * 128;   // [64*32]

        // --- stage 1: ih-GEMM (schunk-major so early chunks finish first) ---
        for (int jb = c0; jb < NGJOB; jb += NCONS) {
            int schunk = jb / 96;
            int r = jb - schunk * 96;
            int b = r / 3;
            int ny = r - b * 3;
            int m0 = b * 512 + schunk * 64;
            gemm_tile(x, W_ih, b_ih, m0, ny * 128, tid, As, Bs);
            if (tid == 0) red_add_release(&g_ihflag[b * 8 + schunk], 1u);
        }

        // --- stage 2: Jacobian, dual-b tiles (W loaded once per pair) ---
        const int w = tid >> 5;             // warp 0..11 -> i rows
        const int lane = tid & 31;
        const int j0 = lane * 4;
        float* jac = out + NB * NO;

        int scready = -1;
        for (int t = c0; t < NS * 16; t += NCONS) {
            int s = t >> 4;
            int b0 = t & 15;                // pair: (s, b0) and (s, b0+16)
            int sc = s >> 3;
            if (sc != scready) {
                if (tid == 0) {
                    while (ld_acquire(&g_flag[sc]) < (unsigned)NB) __nanosleep(128);
                }
                __syncthreads();
                scready = sc;
            }
            const float4* cpA = (const float4*)(g_coef + (size_t)(s * NB + b0) * (4 * NH));
            const float4* cpB = (const float4*)(g_coef + (size_t)(s * NB + b0 + 16) * (4 * NH));
            float4 crA = cpA[lane], cnA = cpA[32 + lane], czA = cpA[64 + lane], zzA = cpA[96 + lane];
            float4 crB = cpB[lane], cnB = cpB[32 + lane], czB = cpB[64 + lane], zzB = cpB[96 + lane];
            float* obA = jac + ((size_t)((NS - 1 - s) * NB + b0)) * (NH * NH);
            float* obB = jac + ((size_t)((NS - 1 - s) * NB + b0 + 16)) * (NH * NH);
            for (int i = w; i < NH; i += 12) {
                const float4* wp = (const float4*)(g_wT + (size_t)i * NG);
                float4 wr = wp[lane];          // W_hh[j, i]
                float4 wz = wp[32 + lane];     // W_hh[H+j, i]
                float4 wn = wp[64 + lane];     // W_hh[2H+j, i]
                float4 vA, vB;
                vA.x = fmaf(wr.x, crA.x, fmaf(wn.x, cnA.x, wz.x * czA.x));
                vA.y = fmaf(wr.y, crA.y, fmaf(wn.y, cnA.y, wz.y * czA.y));
                vA.z = fmaf(wr.z, crA.z, fmaf(wn.z, cnA.z, wz.z * czA.z));
                vA.w = fmaf(wr.w, crA.w, fmaf(wn.w, cnA.w, wz.w * czA.w));
                vB.x = fmaf(wr.x, crB.x, fmaf(wn.x, cnB.x, wz.x * czB.x));
                vB.y = fmaf(wr.y, crB.y, fmaf(wn.y, cnB.y, wz.y * czB.y));
                vB.z = fmaf(wr.z, crB.z, fmaf(wn.z, cnB.z, wz.z * czB.z));
                vB.w = fmaf(wr.w, crB.w, fmaf(wn.w, cnB.w, wz.w * czB.w));
                if ((i >> 2) == lane) {        // diagonal j == i
                    int d = i & 3;
                    if (d == 0) { vA.x += zzA.x; vB.x += zzB.x; }
                    else if (d == 1) { vA.y += zzA.y; vB.y += zzB.y; }
                    else if (d == 2) { vA.z += zzA.z; vB.z += zzB.z; }
                    else { vA.w += zzA.w; vB.w += zzB.w; }
                }
                *(float4*)(obA + i * NH + j0) = vA;
                *(float4*)(obB + i * NH + j0) = vB;
            }
        }
    }
}

// ---------------- launch ----------------
extern "C" void kernel_launch(void* const* d_in, const int* in_sizes, int n_in,
                              void* d_out, int out_size) {
    const float* x    = (const float*)d_in[0];
    const float* W_ih = (const float*)d_in[1];
    const float* W_hh = (const float*)d_in[2];
    const float* b_ih = (const float*)d_in[3];
    const float* b_hh = (const float*)d_in[4];
    const float* W_y  = (const float*)d_in[5];
    const float* b_y  = (const float*)d_in[6];
    float* out = (float*)d_out;

    init_kernel<<<64, 256>>>(W_hh);
    mega_kernel<<<NB + NCONS, NG>>>(x, W_ih, b_ih, W_hh, b_hh, W_y, b_y, out);
}